// round 2
// baseline (speedup 1.0000x reference)
#include <cuda_runtime.h>
#include <cuda_bf16.h>
#include <cstdint>

#define NROWS 8192
#define DIM   512
#define SCALE 2.659f
#define BM 128
#define BN 64
#define LDA 520   // 512 + 8 bf16 pad -> 1040B row stride, conflict-free LDSM

__device__ __nv_bfloat16 g_img[NROWS * DIM];
__device__ __nv_bfloat16 g_txt[NROWS * DIM];
__device__ int   g_lab[NROWS];
__device__ float g_cnt[NROWS];
__device__ float g_rowloss[2 * NROWS];

// ---------------------------------------------------------------------------
// Label prep (single CTA): detect int64-vs-int32 encoding of the labels
// buffer, canonicalize to int g_lab[], then histogram -> per-row target count.
// Reading p[0..8191] as int32 is in-bounds under BOTH dtype hypotheses.
// ---------------------------------------------------------------------------
__global__ void label_prep_kernel(const int* __restrict__ p) {
    __shared__ int viol;
    __shared__ int h[128];
    int tid = threadIdx.x;
    if (tid == 0) viol = 0;
    if (tid < 128) h[tid] = 0;
    __syncthreads();

    // Detection: under int64, odd int32 words are sign-extensions (0 or -1).
    int v = 0;
    for (int i = tid; i < NROWS / 2; i += 256) {
        int hiw = p[2 * i + 1];
        if (hiw != 0 && hiw != -1) v = 1;
    }
    if (v) atomicAdd(&viol, 1);
    __syncthreads();
    bool is64 = (viol == 0);

    for (int i = tid; i < NROWS; i += 256)
        g_lab[i] = is64 ? p[2 * i] : p[i];
    __syncthreads();

    for (int i = tid; i < NROWS; i += 256) {
        int l = g_lab[i];
        if (l >= 0 && l < 128) atomicAdd(&h[l], 1);
    }
    __syncthreads();
    for (int i = tid; i < NROWS; i += 256) {
        int l = g_lab[i];
        g_cnt[i] = (l < 0 || l >= 128) ? 1.0f : (float)h[l];
    }
}

// ---------------------------------------------------------------------------
// Normalize rows to unit L2 norm, write bf16.
// grid (NROWS, 2), block 128. y==0 -> image, y==1 -> text.
// ---------------------------------------------------------------------------
__global__ void normalize_kernel(const float* __restrict__ text,
                                 const float* __restrict__ image) {
    int row = blockIdx.x;
    const float* src = blockIdx.y ? text : image;
    __nv_bfloat16* dst = blockIdx.y ? g_txt : g_img;
    int tid = threadIdx.x, lane = tid & 31, wid = tid >> 5;

    float4 v = ((const float4*)(src + (size_t)row * DIM))[tid];
    float ss = v.x * v.x + v.y * v.y + v.z * v.z + v.w * v.w;
#pragma unroll
    for (int o = 16; o; o >>= 1) ss += __shfl_xor_sync(0xffffffffu, ss, o);
    __shared__ float wss[4];
    if (lane == 0) wss[wid] = ss;
    __syncthreads();
    float tot = wss[0] + wss[1] + wss[2] + wss[3];
    float inv = 1.0f / fmaxf(sqrtf(tot), 1e-12f);

    __nv_bfloat162* dp = (__nv_bfloat162*)(dst + (size_t)row * DIM);
    dp[2 * tid]     = __floats2bfloat162_rn(v.x * inv, v.y * inv);
    dp[2 * tid + 1] = __floats2bfloat162_rn(v.z * inv, v.w * inv);
}

// ---------------------------------------------------------------------------
// Main fused GEMM + softmax-stats kernel.
// grid 128: blocks [0,64) = pass 0 (rows=img, cols=txt),
//           blocks [64,128) = pass 1 (rows=txt, cols=img).
// Each CTA owns BM=128 rows, streams all N cols in BN=64 tiles.
// Per row: sumexp = sum_j exp(S_ij - C),  dotT = sum_j T_ij * S_ij.
// rowloss_i = C + log(sumexp_i) - dotT_i / cnt_i.
// ---------------------------------------------------------------------------
#define MMA_BF16(C, A, B0, B1)                                               \
    asm volatile(                                                            \
        "mma.sync.aligned.m16n8k16.row.col.f32.bf16.bf16.f32 "               \
        "{%0,%1,%2,%3}, {%4,%5,%6,%7}, {%8,%9}, {%0,%1,%2,%3};"              \
        : "+f"((C)[0]), "+f"((C)[1]), "+f"((C)[2]), "+f"((C)[3])             \
        : "r"((A)[0]), "r"((A)[1]), "r"((A)[2]), "r"((A)[3]),                \
          "r"(B0), "r"(B1))

#define LDSM4(R, ADDR)                                                       \
    asm volatile("ldmatrix.sync.aligned.m8n8.x4.shared.b16 {%0,%1,%2,%3}, [%4];" \
                 : "=r"((R)[0]), "=r"((R)[1]), "=r"((R)[2]), "=r"((R)[3])    \
                 : "r"(ADDR))

__global__ __launch_bounds__(256, 1)
void unicl_main_kernel() {
    extern __shared__ char smem[];
    __nv_bfloat16* As = (__nv_bfloat16*)smem;                       // BM x LDA
    __nv_bfloat16* Bs = (__nv_bfloat16*)(smem + BM * LDA * 2);      // BN x LDA
    int*   labj_s = (int*)(smem + (BM + BN) * LDA * 2);             // BN ints
    float* rsum   = (float*)(smem + (BM + BN) * LDA * 2 + 256);     // BM floats
    float* rdot   = rsum + BM;                                      // BM floats

    int tid = threadIdx.x;
    int pass = blockIdx.x >> 6;
    int mb   = blockIdx.x & 63;
    int gm0  = mb * BM;
    const __nv_bfloat16* Ag = pass ? g_txt : g_img;
    const __nv_bfloat16* Bg = pass ? g_img : g_txt;

    int lane = tid & 31, wid = tid >> 5;
    int warp_m = (wid >> 1) * 32;   // 0,32,64,96
    int warp_n = (wid & 1) * 32;    // 0,32
    int g = lane >> 2, tig = lane & 3;

    // Load A block (128 x 512 bf16) into smem, 16B per thread per step.
    for (int idx = tid; idx < BM * 64; idx += 256) {
        int r = idx >> 6, c = idx & 63;
        uint4 v = ((const uint4*)(Ag + (size_t)(gm0 + r) * DIM))[c];
        *(uint4*)(As + r * LDA + c * 8) = v;
    }
    if (tid < BM) { rsum[tid] = 0.0f; rdot[tid] = 0.0f; }

    uint32_t As_u = (uint32_t)__cvta_generic_to_shared(As);
    uint32_t Bs_u = (uint32_t)__cvta_generic_to_shared(Bs);

    // ldmatrix lane addressing
    int a_row = warp_m + (lane & 15);
    int a_k8  = (lane >> 4) << 3;
    uint32_t addrA0 = As_u + (uint32_t)((a_row)      * LDA + a_k8) * 2;
    uint32_t addrA1 = As_u + (uint32_t)((a_row + 16) * LDA + a_k8) * 2;
    int b_n  = warp_n + (lane & 7) + ((lane >> 4) << 3);
    int b_k8 = ((lane >> 3) & 1) << 3;
    uint32_t addrB0 = Bs_u + (uint32_t)((b_n)      * LDA + b_k8) * 2;
    uint32_t addrB1 = Bs_u + (uint32_t)((b_n + 16) * LDA + b_k8) * 2;

    // The 4 global rows this thread's C fragments touch (fixed for all tiles)
    int gr[4]; int labi[4];
#pragma unroll
    for (int i = 0; i < 4; i++) {
        gr[i]   = gm0 + warp_m + 16 * (i >> 1) + 8 * (i & 1) + g;
        labi[i] = g_lab[gr[i]];
    }

    float acc_se[4]  = {0.f, 0.f, 0.f, 0.f};
    float acc_dot[4] = {0.f, 0.f, 0.f, 0.f};

    for (int jt = 0; jt < NROWS / BN; jt++) {
        int jbase = jt * BN;
        __syncthreads();   // protect Bs/labj_s from prior iteration's readers
        for (int idx = tid; idx < BN * 64; idx += 256) {
            int r = idx >> 6, c = idx & 63;
            uint4 v = ((const uint4*)(Bg + (size_t)(jbase + r) * DIM))[c];
            *(uint4*)(Bs + r * LDA + c * 8) = v;
        }
        if (tid < BN) labj_s[tid] = g_lab[jbase + tid];
        __syncthreads();

        float cf[2][4][4];
#pragma unroll
        for (int t = 0; t < 2; t++)
#pragma unroll
            for (int n = 0; n < 4; n++)
#pragma unroll
                for (int e = 0; e < 4; e++) cf[t][n][e] = 0.0f;

#pragma unroll
        for (int ks = 0; ks < DIM / 16; ks++) {
            uint32_t koff = ks * 32;   // 16 bf16 = 32 bytes
            uint32_t a0[4], a1[4], bA[4], bB[4];
            LDSM4(a0, addrA0 + koff);
            LDSM4(a1, addrA1 + koff);
            LDSM4(bA, addrB0 + koff);  // n-tiles 0,1
            LDSM4(bB, addrB1 + koff);  // n-tiles 2,3
            MMA_BF16(cf[0][0], a0, bA[0], bA[1]);
            MMA_BF16(cf[0][1], a0, bA[2], bA[3]);
            MMA_BF16(cf[0][2], a0, bB[0], bB[1]);
            MMA_BF16(cf[0][3], a0, bB[2], bB[3]);
            MMA_BF16(cf[1][0], a1, bA[0], bA[1]);
            MMA_BF16(cf[1][1], a1, bA[2], bA[3]);
            MMA_BF16(cf[1][2], a1, bB[0], bB[1]);
            MMA_BF16(cf[1][3], a1, bB[2], bB[3]);
        }

        // Epilogue: accumulate exp(S - C) and T*S into per-thread row accums.
#pragma unroll
        for (int t = 0; t < 2; t++) {
#pragma unroll
            for (int nt = 0; nt < 4; nt++) {
#pragma unroll
                for (int e = 0; e < 4; e++) {
                    int u = e >> 1, h = e & 1;
                    int ri = t * 2 + u;
                    float s = SCALE * cf[t][nt][e];
                    acc_se[ri] += __expf(s - SCALE);
                    int cl = warp_n + nt * 8 + tig * 2 + h;
                    int lj = labj_s[cl];
                    bool w = ((jbase + cl) == gr[ri]) ||
                             (labi[ri] >= 0 && lj == labi[ri]);
                    if (w) acc_dot[ri] += s;
                }
            }
        }
    }

    // Reduce across the quad (lanes sharing a row), then across the 2 n-warps.
#pragma unroll
    for (int i = 0; i < 4; i++) {
        float se = acc_se[i], dt = acc_dot[i];
        se += __shfl_xor_sync(0xffffffffu, se, 1);
        se += __shfl_xor_sync(0xffffffffu, se, 2);
        dt += __shfl_xor_sync(0xffffffffu, dt, 1);
        dt += __shfl_xor_sync(0xffffffffu, dt, 2);
        if (tig == 0) {
            int rl = warp_m + 16 * (i >> 1) + 8 * (i & 1) + g;
            atomicAdd(&rsum[rl], se);   // exactly 2 adds per row -> deterministic
            atomicAdd(&rdot[rl], dt);
        }
    }
    __syncthreads();
    if (tid < BM) {
        int gi = gm0 + tid;
        float loss = SCALE + logf(rsum[tid]) - rdot[tid] / g_cnt[gi];
        g_rowloss[pass * NROWS + gi] = loss;
    }
}

// ---------------------------------------------------------------------------
// Deterministic final reduction: mean over 2N row losses / 2.
// ---------------------------------------------------------------------------
__global__ void reduce_kernel(float* __restrict__ out) {
    __shared__ float sh[256];
    int tid = threadIdx.x;
    float s = 0.0f;
    for (int i = tid; i < 2 * NROWS; i += 256) s += g_rowloss[i];
    sh[tid] = s;
    __syncthreads();
    for (int o = 128; o; o >>= 1) {
        if (tid < o) sh[tid] += sh[tid + o];
        __syncthreads();
    }
    if (tid == 0) out[0] = sh[0] * (1.0f / (2.0f * NROWS));
}

// ---------------------------------------------------------------------------
extern "C" void kernel_launch(void* const* d_in, const int* in_sizes, int n_in,
                              void* d_out, int out_size) {
    const float* text   = (const float*)d_in[0];
    const float* image  = (const float*)d_in[1];
    const int*   labels = (const int*)d_in[2];
    float* out = (float*)d_out;

    label_prep_kernel<<<1, 256>>>(labels);
    normalize_kernel<<<dim3(NROWS, 2), 128>>>(text, image);

    int smem_bytes = (BM + BN) * LDA * 2 + 256 + 2 * BM * 4;  // 200960 B
    cudaFuncSetAttribute(unicl_main_kernel,
                         cudaFuncAttributeMaxDynamicSharedMemorySize, smem_bytes);
    unicl_main_kernel<<<128, 256, smem_bytes>>>();

    reduce_kernel<<<1, 256>>>(out);
}

// round 4
// speedup vs baseline: 2.0023x; 2.0023x over previous
#include <cuda_runtime.h>
#include <cuda_bf16.h>
#include <cstdint>

#define NROWS 8192
#define DIM   512
#define SCALE 2.659f

__device__ __nv_bfloat16 g_img[NROWS * DIM];
__device__ __nv_bfloat16 g_txt[NROWS * DIM];
__device__ int   g_key[NROWS];
__device__ float g_cnt[NROWS];
__device__ float g_rowsum[NROWS];
__device__ float g_rowdot[NROWS];
__device__ float g_colsum[NROWS];
__device__ float g_coldot[NROWS];

// ---------------- asm helpers ----------------
#define MMA_BF16(C, A, B0, B1)                                               \
    asm volatile(                                                            \
        "mma.sync.aligned.m16n8k16.row.col.f32.bf16.bf16.f32 "               \
        "{%0,%1,%2,%3}, {%4,%5,%6,%7}, {%8,%9}, {%0,%1,%2,%3};"              \
        : "+f"((C)[0]), "+f"((C)[1]), "+f"((C)[2]), "+f"((C)[3])             \
        : "r"((A)[0]), "r"((A)[1]), "r"((A)[2]), "r"((A)[3]),                \
          "r"(B0), "r"(B1))

#define LDSM4(R, ADDR)                                                       \
    asm volatile("ldmatrix.sync.aligned.m8n8.x4.shared.b16 {%0,%1,%2,%3}, [%4];" \
                 : "=r"((R)[0]), "=r"((R)[1]), "=r"((R)[2]), "=r"((R)[3])    \
                 : "r"(ADDR))

#define CP_ASYNC16(dst, src)                                                 \
    asm volatile("cp.async.cg.shared.global [%0], [%1], 16;"                 \
                 :: "r"(dst), "l"(src))
#define CP_COMMIT() asm volatile("cp.async.commit_group;" ::: "memory")
#define CP_WAIT(N)  asm volatile("cp.async.wait_group %0;" :: "n"(N) : "memory")

// ---------------------------------------------------------------------------
// Label prep (1 CTA): dtype sniff (int64 vs int32), canonical keys,
// histogram counts, and zeroing of the global accumulators.
// ---------------------------------------------------------------------------
__global__ void label_prep_kernel(const int* __restrict__ p) {
    __shared__ int viol;
    __shared__ int h[128];
    int tid = threadIdx.x;
    if (tid == 0) viol = 0;
    if (tid < 128) h[tid] = 0;
    __syncthreads();
    int v = 0;
    for (int i = tid; i < NROWS / 2; i += 256) {
        int hiw = p[2 * i + 1];
        if (hiw != 0 && hiw != -1) v = 1;
    }
    if (v) atomicAdd(&viol, 1);
    __syncthreads();
    bool is64 = (viol == 0);
    for (int i = tid; i < NROWS; i += 256) {
        int l = is64 ? p[2 * i] : p[i];
        g_key[i] = (l >= 0 && l < 128) ? l : (1 << 20) + i;
        if (l >= 0 && l < 128) atomicAdd(&h[l], 1);
        g_rowsum[i] = 0.0f; g_rowdot[i] = 0.0f;
        g_colsum[i] = 0.0f; g_coldot[i] = 0.0f;
    }
    __syncthreads();
    for (int i = tid; i < NROWS; i += 256) {
        int k = g_key[i];
        g_cnt[i] = (k < 128) ? (float)h[k] : 1.0f;
    }
}

// ---------------------------------------------------------------------------
// Normalize rows to unit L2, write bf16.
// ---------------------------------------------------------------------------
__global__ void normalize_kernel(const float* __restrict__ text,
                                 const float* __restrict__ image) {
    int row = blockIdx.x;
    const float* src = blockIdx.y ? text : image;
    __nv_bfloat16* dst = blockIdx.y ? g_txt : g_img;
    int tid = threadIdx.x, lane = tid & 31, wid = tid >> 5;

    float4 v = ((const float4*)(src + (size_t)row * DIM))[tid];
    float ss = v.x * v.x + v.y * v.y + v.z * v.z + v.w * v.w;
#pragma unroll
    for (int o = 16; o; o >>= 1) ss += __shfl_xor_sync(0xffffffffu, ss, o);
    __shared__ float wss[4];
    if (lane == 0) wss[wid] = ss;
    __syncthreads();
    float tot = wss[0] + wss[1] + wss[2] + wss[3];
    float inv = 1.0f / fmaxf(sqrtf(tot), 1e-12f);

    __nv_bfloat162* dp = (__nv_bfloat162*)(dst + (size_t)row * DIM);
    dp[2 * tid]     = __floats2bfloat162_rn(v.x * inv, v.y * inv);
    dp[2 * tid + 1] = __floats2bfloat162_rn(v.z * inv, v.w * inv);
}

// ---------------------------------------------------------------------------
// Main kernel: single pass over S = img_n @ txt_n^T.
// grid (64, 16): x = m-block (128 rows of img), y = n-group (512 cols of txt,
// processed as 4 sub-tiles of 128). A panel (128x512) resident in smem;
// B streamed through a 4-stage cp.async ring (stage = 128 rows x 64 k).
// Per tile: row stats (exp-sum, T.S-dot) and col stats accumulated; flushed
// once per CTA via global atomics.
// ---------------------------------------------------------------------------
__global__ __launch_bounds__(256, 1)
void unicl_gemm_kernel() {
    extern __shared__ char sm[];
    uint32_t sbase = (uint32_t)__cvta_generic_to_shared(sm);
    const uint32_t As_u = sbase;                 // [8 ksteps][128 rows][64 k] bf16
    const uint32_t Bs_u = sbase + 131072u;       // 4 stages x [128][64]
    int*   keys_s = (int*)(sm + 196608);         // 512 col keys
    float* row_se = (float*)(sm + 198656);       // 128
    float* row_dt = row_se + 128;                // 128
    float* col_se = (float*)(sm + 199680);       // 512
    float* col_dt = col_se + 512;                // 512

    int tid = threadIdx.x, lane = tid & 31, wid = tid >> 5;
    int gm0 = blockIdx.x * 128;
    int n0  = blockIdx.y * 512;
    const __nv_bfloat16* Ag = g_img;
    const __nv_bfloat16* Bg = g_txt;

    for (int i = tid; i < 128; i += 256) { row_se[i] = 0.0f; row_dt[i] = 0.0f; }
    for (int i = tid; i < 512; i += 256) {
        col_se[i] = 0.0f; col_dt[i] = 0.0f;
        keys_s[i] = g_key[n0 + i];
    }

    // --- A prologue: 128x512 bf16 = 8192 16B-chunks, 32 per thread ---
#pragma unroll
    for (int q = 0; q < 32; q++) {
        int idx = tid + q * 256;
        int s8 = idx >> 10, row = (idx >> 3) & 127, ch = idx & 7;
        const void* src = Ag + (size_t)(gm0 + row) * DIM + s8 * 64 + ch * 8;
        uint32_t dst = As_u + s8 * 16384 + row * 128 + ((ch ^ (row & 7)) << 4);
        CP_ASYNC16(dst, src);
    }
    CP_COMMIT();

    // --- B stage issue helper ---
    auto issueB = [&](int gs) {
        int t = gs >> 3, s8 = gs & 7;
        const __nv_bfloat16* bsrc = Bg + (size_t)(n0 + t * 128) * DIM + s8 * 64;
        uint32_t bdst = Bs_u + (gs & 3) * 16384;
#pragma unroll
        for (int q = 0; q < 4; q++) {
            int idx = tid + q * 256;
            int row = idx >> 3, ch = idx & 7;
            CP_ASYNC16(bdst + row * 128 + ((ch ^ (row & 7)) << 4),
                       bsrc + (size_t)row * DIM + ch * 8);
        }
    };
    issueB(0); CP_COMMIT();
    issueB(1); CP_COMMIT();
    issueB(2); CP_COMMIT();

    // --- per-warp geometry ---
    int warp_mI = (wid & 3) * 32;        // 4 m-warps
    int warp_nB = (wid >> 2) * 64;       // 2 n-warps
    int g = lane >> 2, tig = lane & 3;
    uint32_t rA0b = (uint32_t)(warp_mI + (lane & 15)) * 128;
    uint32_t r7A  = (uint32_t)(lane & 7);
    uint32_t hiA  = (uint32_t)(lane >> 4);
    int rB0 = warp_nB + (lane & 7) + ((lane >> 4) << 3);
    uint32_t rB0b = (uint32_t)rB0 * 128;
    uint32_t r7B  = (uint32_t)(lane & 7);
    uint32_t hiB  = (uint32_t)((lane >> 3) & 1);

    int mykey[4];
#pragma unroll
    for (int ri = 0; ri < 4; ri++)
        mykey[ri] = g_key[gm0 + warp_mI + g + ri * 8];

    float rse[4] = {0.f, 0.f, 0.f, 0.f};
    float rdt[4] = {0.f, 0.f, 0.f, 0.f};
    const float K2 = SCALE * 1.44269504f;

    for (int t = 0; t < 4; t++) {
        float c[2][8][4];
#pragma unroll
        for (int mf = 0; mf < 2; mf++)
#pragma unroll
            for (int nf = 0; nf < 8; nf++)
#pragma unroll
                for (int e = 0; e < 4; e++) c[mf][nf][e] = 0.0f;

#pragma unroll 1
        for (int s8 = 0; s8 < 8; s8++) {
            int gs = t * 8 + s8;
            if (gs < 30)      { CP_WAIT(2); }
            else if (gs == 30){ CP_WAIT(1); }
            else              { CP_WAIT(0); }
            __syncthreads();
            if (gs < 29) { issueB(gs + 3); CP_COMMIT(); }

            uint32_t Ab = As_u + s8 * 16384;
            uint32_t Bb = Bs_u + (gs & 3) * 16384;
#pragma unroll
            for (int k16 = 0; k16 < 4; k16++) {
                uint32_t a0[4], a1[4], b0[4], b1[4], b2[4], b3[4];
                uint32_t cA = ((k16 * 2 + hiA) ^ r7A) << 4;
                LDSM4(a0, Ab + rA0b + cA);
                LDSM4(a1, Ab + rA0b + 2048 + cA);
                uint32_t cB = ((k16 * 2 + hiB) ^ r7B) << 4;
                LDSM4(b0, Bb + rB0b + cB);
                LDSM4(b1, Bb + rB0b + 2048 + cB);
                LDSM4(b2, Bb + rB0b + 4096 + cB);
                LDSM4(b3, Bb + rB0b + 6144 + cB);
                MMA_BF16(c[0][0], a0, b0[0], b0[1]);
                MMA_BF16(c[0][1], a0, b0[2], b0[3]);
                MMA_BF16(c[0][2], a0, b1[0], b1[1]);
                MMA_BF16(c[0][3], a0, b1[2], b1[3]);
                MMA_BF16(c[0][4], a0, b2[0], b2[1]);
                MMA_BF16(c[0][5], a0, b2[2], b2[3]);
                MMA_BF16(c[0][6], a0, b3[0], b3[1]);
                MMA_BF16(c[0][7], a0, b3[2], b3[3]);
                MMA_BF16(c[1][0], a1, b0[0], b0[1]);
                MMA_BF16(c[1][1], a1, b0[2], b0[3]);
                MMA_BF16(c[1][2], a1, b1[0], b1[1]);
                MMA_BF16(c[1][3], a1, b1[2], b1[3]);
                MMA_BF16(c[1][4], a1, b2[0], b2[1]);
                MMA_BF16(c[1][5], a1, b2[2], b2[3]);
                MMA_BF16(c[1][6], a1, b3[0], b3[1]);
                MMA_BF16(c[1][7], a1, b3[2], b3[3]);
            }
        }

        // --- epilogue for sub-tile t ---
        float cse[16], cdt[16];
#pragma unroll
        for (int p = 0; p < 16; p++) { cse[p] = 0.0f; cdt[p] = 0.0f; }
        const int* ks = keys_s + t * 128 + warp_nB;
#pragma unroll
        for (int mf = 0; mf < 2; mf++) {
#pragma unroll
            for (int nf = 0; nf < 8; nf++) {
#pragma unroll
                for (int e = 0; e < 4; e++) {
                    float cv = c[mf][nf][e];
                    float ex;
                    asm("ex2.approx.ftz.f32 %0, %1;" : "=f"(ex)
                        : "f"(fmaf(cv, K2, -K2)));
                    int ri = mf * 2 + (e >> 1);
                    int p  = nf * 2 + (e & 1);
                    rse[ri] += ex;
                    cse[p]  += ex;
                    int key = ks[nf * 8 + tig * 2 + (e & 1)];
                    if (key == mykey[ri]) { rdt[ri] += cv; cdt[p] += cv; }
                }
            }
        }
        // reduce columns across the 8 row-groups (g) of the warp
#pragma unroll
        for (int p = 0; p < 16; p++) {
            cse[p] += __shfl_xor_sync(0xffffffffu, cse[p], 4);
            cse[p] += __shfl_xor_sync(0xffffffffu, cse[p], 8);
            cse[p] += __shfl_xor_sync(0xffffffffu, cse[p], 16);
            cdt[p] += __shfl_xor_sync(0xffffffffu, cdt[p], 4);
            cdt[p] += __shfl_xor_sync(0xffffffffu, cdt[p], 8);
            cdt[p] += __shfl_xor_sync(0xffffffffu, cdt[p], 16);
        }
        // lane g writes positions 2g, 2g+1 (each a distinct column for its tig)
#pragma unroll
        for (int q = 0; q < 2; q++) {
            int p = g * 2 + q;
            int cidx = t * 128 + warp_nB + (p >> 1) * 8 + tig * 2 + (p & 1);
            atomicAdd(&col_se[cidx], cse[p]);
            atomicAdd(&col_dt[cidx], cdt[p]);
        }
    }

    // --- row reduction (over tig) + CTA flush ---
#pragma unroll
    for (int ri = 0; ri < 4; ri++) {
        float v = rse[ri];
        v += __shfl_xor_sync(0xffffffffu, v, 1);
        v += __shfl_xor_sync(0xffffffffu, v, 2);
        float w = rdt[ri];
        w += __shfl_xor_sync(0xffffffffu, w, 1);
        w += __shfl_xor_sync(0xffffffffu, w, 2);
        if (tig == 0) {
            atomicAdd(&row_se[warp_mI + g + ri * 8], v);
            atomicAdd(&row_dt[warp_mI + g + ri * 8], w);
        }
    }
    __syncthreads();
    for (int i = tid; i < 128; i += 256) {
        atomicAdd(&g_rowsum[gm0 + i], row_se[i]);
        atomicAdd(&g_rowdot[gm0 + i], row_dt[i]);
    }
    for (int i = tid; i < 512; i += 256) {
        atomicAdd(&g_colsum[n0 + i], col_se[i]);
        atomicAdd(&g_coldot[n0 + i], col_dt[i]);
    }
}

// ---------------------------------------------------------------------------
// Final loss: per-row losses for both directions, mean / 2.
// ---------------------------------------------------------------------------
__global__ void loss_kernel(float* __restrict__ out) {
    __shared__ float sh[1024];
    int tid = threadIdx.x;
    float s = 0.0f;
    for (int i = tid; i < NROWS; i += 1024) {
        float inv = SCALE / g_cnt[i];
        s += 2.0f * SCALE + logf(g_rowsum[i]) + logf(g_colsum[i])
             - (g_rowdot[i] + g_coldot[i]) * inv;
    }
    sh[tid] = s;
    __syncthreads();
    for (int o = 512; o; o >>= 1) {
        if (tid < o) sh[tid] += sh[tid + o];
        __syncthreads();
    }
    if (tid == 0) out[0] = sh[0] * (1.0f / (2.0f * NROWS));
}

// ---------------------------------------------------------------------------
extern "C" void kernel_launch(void* const* d_in, const int* in_sizes, int n_in,
                              void* d_out, int out_size) {
    const float* text   = (const float*)d_in[0];
    const float* image  = (const float*)d_in[1];
    const int*   labels = (const int*)d_in[2];
    float* out = (float*)d_out;

    label_prep_kernel<<<1, 256>>>(labels);
    normalize_kernel<<<dim3(NROWS, 2), 128>>>(text, image);

    int smem_bytes = 203776;
    cudaFuncSetAttribute(unicl_gemm_kernel,
                         cudaFuncAttributeMaxDynamicSharedMemorySize, smem_bytes);
    unicl_gemm_kernel<<<dim3(64, 16), 256, smem_bytes>>>();

    loss_kernel<<<1, 1024>>>(out);
}